// round 5
// baseline (speedup 1.0000x reference)
#include <cuda_runtime.h>
#include <math.h>

#define NPIX 256
#define TPB 352      // 11 warps; 143 blocks => exactly 1 wave on 148 SMs
#define YTILE 32     // rows staged in SMEM per tile (32 KB)

typedef unsigned long long ull;

// Transposed preprocessed image: d_imgT[x * NPIX + y]
__device__ __align__(16) float d_imgT[NPIX * NPIX];

// ---- packed f32x2 helpers (Blackwell FFMA2 path) ----
__device__ __forceinline__ ull pack2(float lo, float hi) {
    ull r; asm("mov.b64 %0, {%1,%2};" : "=l"(r) : "f"(lo), "f"(hi)); return r;
}
__device__ __forceinline__ void unpack2(ull v, float& lo, float& hi) {
    asm("mov.b64 {%0,%1}, %2;" : "=f"(lo), "=f"(hi) : "l"(v));
}
#define FMA2(d, a, b, c) asm("fma.rn.f32x2 %0, %1, %2, %3;" : "=l"(d) : "l"(a), "l"(b), "l"(c))
#define MUL2(d, a, b)    asm("mul.rn.f32x2 %0, %1, %2;"     : "=l"(d) : "l"(a), "l"(b))

// Kernel 1: img = HannConv3x3(softplus(base)), zero-padded SAME, stored TRANSPOSED.
__global__ void prep_kernel(const float* __restrict__ base) {
    int idx = blockIdx.x * blockDim.x + threadIdx.x;
    if (idx >= NPIX * NPIX) return;
    int px = idx & (NPIX - 1);
    int py = idx >> 8;
    const float w[3] = {0.25f, 0.5f, 0.25f};
    float acc = 0.f;
#pragma unroll
    for (int dy = -1; dy <= 1; ++dy) {
#pragma unroll
        for (int dx = -1; dx <= 1; ++dx) {
            int yy = py + dy, xx = px + dx;
            if (yy >= 0 && yy < NPIX && xx >= 0 && xx < NPIX) {
                float v = base[yy * NPIX + xx];
                float sp = fmaxf(v, 0.f) + log1pf(expf(-fabsf(v)));  // stable softplus
                acc += w[dy + 1] * w[dx + 1] * sp;
            }
        }
    }
    d_imgT[px * NPIX + py] = acc;   // transposed store
}

// Kernel 2: exact type-2 NUDFT, packed f32x2 datapath.
// vis[k] = cell^2 * e^{+2pi*i*128*(fu+fv)} * sum_y e^{-2pi*i*fv*y} sum_x img[y,x] e^{-2pi*i*fu*x}
// Lanes of every f32x2 = two adjacent image rows (same x => same twiddle).
__global__ void __launch_bounds__(TPB)
vis_kernel(const float* __restrict__ uu,
           const float* __restrict__ vv,
           float* __restrict__ out, int nvis, int mode) {
    // st[x][j]: YTILE y-values contiguous per x -> double2 load = rows j0..j0+3 at x
    __shared__ __align__(16) float st[NPIX][YTILE];

    const int k = blockIdx.x * TPB + threadIdx.x;
    const float ARCSEC_F = (float)(M_PI / 180.0 / 3600.0);
    const float cell_rad = 0.005f * ARCSEC_F;

    float fu = 0.f, fv = 0.f;
    if (k < nvis) {
        fu = (uu[k] * 1e3f) * cell_rad;   // cycles per pixel in x, |fu| <= 0.25
        fv = (vv[k] * 1e3f) * cell_rad;
    }

    // x-twiddle table wt[r] = w^r, r=0..15, broadcast-packed. w = exp(-2*pi*i*fu).
    float wur, wui; sincospif(-2.f * fu, &wui, &wur);
    ull wtr2[16], wti2[16];
    {
        float tr = 1.f, ti = 0.f;
        wtr2[0] = pack2(1.f, 1.f); wti2[0] = pack2(0.f, 0.f);
#pragma unroll
        for (int r = 1; r < 16; ++r) {
            float nr = tr * wur - ti * wui;
            float ni = tr * wui + ti * wur;
            tr = nr; ti = ni;
            wtr2[r] = pack2(tr, tr); wti2[r] = pack2(ti, ti);
        }
    }
    // W16 = w^16 (exact seed)
    float W16r, W16i; sincospif(-32.f * fu, &W16i, &W16r);
    const ull W16r2  = pack2(W16r, W16r);
    const ull W16i2  = pack2(W16i, W16i);
    const ull nW16i2 = pack2(-W16i, -W16i);

    // y-phase steps
    float wvr, wvi;   sincospif(-2.f * fv, &wvi, &wvr);   // wv = exp(-2*pi*i*fv)
    float Wv4r, Wv4i; sincospif(-8.f * fv, &Wv4i, &Wv4r); // wv^4
    const ull Wv4r2  = pack2(Wv4r, Wv4r);
    const ull Wv4i2  = pack2(Wv4i, Wv4i);
    const ull nWv4i2 = pack2(-Wv4i, -Wv4i);

    const ull Z2 = pack2(0.f, 0.f);
    ull visR0 = Z2, visI0 = Z2, visR1 = Z2, visI1 = Z2;

    for (int y0 = 0; y0 < NPIX; y0 += YTILE) {
        __syncthreads();
        // Stage: st[x][j] = imgT[x][y0+j]; contiguous global float4 per (x, 4j)
        for (int i = threadIdx.x; i < NPIX * (YTILE / 4); i += TPB) {
            int x = i >> 3, c = i & 7;
            float4 v = *(const float4*)&d_imgT[x * NPIX + y0 + 4 * c];
            *(float4*)&st[x][4 * c] = v;
        }
        __syncthreads();

        // b seeds for this tile: b_y = exp(-2*pi*i*fv*y), exact reseed (no drift)
        float b0r, b0i; sincospif(-2.f * fv * (float)y0, &b0i, &b0r);
        float b1r = b0r * wvr - b0i * wvi, b1i = b0r * wvi + b0i * wvr;
        float b2r = b1r * wvr - b1i * wvi, b2i = b1r * wvi + b1i * wvr;
        float b3r = b2r * wvr - b2i * wvi, b3i = b2r * wvi + b2i * wvr;
        ull bR0 = pack2(b0r, b1r), bI0 = pack2(b0i, b1i), nbI0 = pack2(-b0i, -b1i);
        ull bR1 = pack2(b2r, b3r), bI1 = pack2(b2i, b3i), nbI1 = pack2(-b2i, -b3i);

        for (int j0 = 0; j0 < YTILE; j0 += 4) {     // 4 rows per pass
            ull AR2 = pack2(1.f, 1.f), AI2 = Z2, nAI2 = Z2;   // A = W16^q
            ull rowR0 = Z2, rowI0 = Z2, rowR1 = Z2, rowI1 = Z2;
            const char* stp = (const char*)&st[0][j0];

            for (int q = 0; q < 16; ++q) {
                ull pr0 = Z2, pi0 = Z2, pr1 = Z2, pi1 = Z2;
#pragma unroll
                for (int r = 0; r < 16; ++r) {
                    // rows (j0..j0+3) at x = 16q + r : one broadcast LDS.128
                    const double2 dd = *(const double2*)(stp + (q * 16 + r) * (YTILE * 4));
                    ull p01 = __double_as_longlong(dd.x);
                    ull p23 = __double_as_longlong(dd.y);
                    FMA2(pr0, p01, wtr2[r], pr0); FMA2(pi0, p01, wti2[r], pi0);
                    FMA2(pr1, p23, wtr2[r], pr1); FMA2(pi1, p23, wti2[r], pi1);
                }
                // row += p * A   (complex, A broadcast in both lanes)
                FMA2(rowR0, pr0, AR2, rowR0); FMA2(rowR0, pi0, nAI2, rowR0);
                FMA2(rowI0, pr0, AI2, rowI0); FMA2(rowI0, pi0, AR2, rowI0);
                FMA2(rowR1, pr1, AR2, rowR1); FMA2(rowR1, pi1, nAI2, rowR1);
                FMA2(rowI1, pr1, AI2, rowI1); FMA2(rowI1, pi1, AR2, rowI1);
                // A *= W16
                ull t0, t1, t2, ARn, AIn, nAIn;
                MUL2(t0, nAI2, W16i2); FMA2(ARn,  AR2, W16r2,  t0);
                MUL2(t1, AI2,  W16r2); FMA2(AIn,  AR2, W16i2,  t1);
                MUL2(t2, nAI2, W16r2); FMA2(nAIn, AR2, nW16i2, t2);
                AR2 = ARn; AI2 = AIn; nAI2 = nAIn;
            }
            // vis += row * b  (lane-wise complex; lanes carry adjacent rows)
            FMA2(visR0, rowR0, bR0, visR0); FMA2(visR0, rowI0, nbI0, visR0);
            FMA2(visI0, rowR0, bI0, visI0); FMA2(visI0, rowI0, bR0, visI0);
            FMA2(visR1, rowR1, bR1, visR1); FMA2(visR1, rowI1, nbI1, visR1);
            FMA2(visI1, rowR1, bI1, visI1); FMA2(visI1, rowI1, bR1, visI1);
            // b *= wv^4 (both pairs)
            ull u0, u1, u2, nR, nI, nnI;
            MUL2(u0, nbI0, Wv4i2); FMA2(nR,  bR0, Wv4r2,  u0);
            MUL2(u1, bI0,  Wv4r2); FMA2(nI,  bR0, Wv4i2,  u1);
            MUL2(u2, nbI0, Wv4r2); FMA2(nnI, bR0, nWv4i2, u2);
            bR0 = nR; bI0 = nI; nbI0 = nnI;
            MUL2(u0, nbI1, Wv4i2); FMA2(nR,  bR1, Wv4r2,  u0);
            MUL2(u1, bI1,  Wv4r2); FMA2(nI,  bR1, Wv4i2,  u1);
            MUL2(u2, nbI1, Wv4r2); FMA2(nnI, bR1, nWv4i2, u2);
            bR1 = nR; bI1 = nI; nbI1 = nnI;
        }
    }

    if (k < nvis) {
        float a0, a1, c0, c1, e0, e1, g0, g1;
        unpack2(visR0, a0, a1); unpack2(visR1, c0, c1);
        unpack2(visI0, e0, e1); unpack2(visI1, g0, g1);
        float visr = (a0 + a1) + (c0 + c1);
        float visi = (e0 + e1) + (g0 + g1);
        // centering phase: exp(+2*pi*i*128*(fu+fv)) — exact, applied once
        float Sr, Si; sincospif(256.f * fu + 256.f * fv, &Si, &Sr);
        float c2 = cell_rad * cell_rad;
        float orr = (visr * Sr - visi * Si) * c2;
        float oii = (visr * Si + visi * Sr) * c2;
        if (mode == 0) {
            out[k] = orr;
        } else {
            out[2 * k + 0] = orr;
            out[2 * k + 1] = oii;
        }
    }
}

extern "C" void kernel_launch(void* const* d_in, const int* in_sizes, int n_in,
                              void* d_out, int out_size) {
    // Input mapping by size: image is uniquely the 65536-element input;
    // the remaining two, in order, are uu then vv. (This fixed R1/R2.)
    int img_i = -1;
    for (int i = 0; i < n_in; ++i)
        if (in_sizes[i] == NPIX * NPIX) { img_i = i; break; }
    if (img_i < 0) img_i = 0;
    int uv_idx[2]; int c = 0;
    for (int i = 0; i < n_in && c < 2; ++i)
        if (i != img_i) uv_idx[c++] = i;

    const float* base = (const float*)d_in[img_i];
    const float* uu   = (const float*)d_in[uv_idx[0]];
    const float* vv   = (const float*)d_in[uv_idx[1]];
    float* out = (float*)d_out;
    const int nvis = in_sizes[uv_idx[0]];

    // Same output-mode logic that passed in R4.
    int mode = (out_size >= 2 * nvis) ? 1 : 0;

    prep_kernel<<<(NPIX * NPIX + 255) / 256, 256>>>(base);
    int blocks = (nvis + TPB - 1) / TPB;   // 143 for nvis=50000 -> single wave
    vis_kernel<<<blocks, TPB>>>(uu, vv, out, nvis, mode);
}